// round 2
// baseline (speedup 1.0000x reference)
#include <cuda_runtime.h>

#define NN 40960
#define PT (4*NN)

__device__ float g_f[(long)PT*32];   // f = relu(s2*(W2@feat)+b2), [point][32]
__device__ float g_z[(long)PT*32];   // z = s3 * (W3a @ f), [point][32]
__device__ int g_is64;

__device__ __forceinline__ unsigned long long pack2(float lo, float hi){
    unsigned long long r;
    asm("mov.b64 %0, {%1, %2};" : "=l"(r) : "f"(lo), "f"(hi));
    return r;
}
__device__ __forceinline__ void unpack2(unsigned long long v, float& lo, float& hi){
    asm("mov.b64 {%0, %1}, %2;" : "=f"(lo), "=f"(hi) : "l"(v));
}
__device__ __forceinline__ unsigned long long fma2(unsigned long long a, unsigned long long b, unsigned long long c){
    unsigned long long d;
    asm("fma.rn.f32x2 %0, %1, %2, %3;" : "=l"(d) : "l"(a), "l"(b), "l"(c));
    return d;
}

// ---------------------------------------------------------------------------
__global__ void detect_idx_kernel(const int* __restrict__ neigh32){
    if (threadIdx.x == 0){
        int allzero = 1;
        #pragma unroll 1
        for (int i = 0; i < 128; i++)
            if (neigh32[2*i + 1] != 0) { allzero = 0; break; }
        g_is64 = allzero;
    }
}

// ---------------------------------------------------------------------------
// Kernel A: per point  f = relu(s2*(W2@x)+b2);  z = s3*(W3a@f)
// block = 64 points of one batch; feature staged transposed in smem.
__global__ void __launch_bounds__(256) kernelA(
    const float* __restrict__ feat,
    const float* __restrict__ W2, const float* __restrict__ g2, const float* __restrict__ b2,
    const float* __restrict__ W3, const float* __restrict__ g3)
{
    __shared__ __align__(8) float tile[64*66];   // [n][d], pad 66
    __shared__ __align__(8) float hs[8][32];

    const int tid  = threadIdx.x;
    const int lane = tid & 31;
    const int wid  = tid >> 5;
    const int b    = blockIdx.x / 640;
    const int n0   = (blockIdx.x - b*640) * 64;
    const float* fb = feat + (long)b*64*NN;

    // stage [64 d][64 n] transposed -> tile[n][d]
    for (int i = tid; i < 4096; i += 256){
        int d = i >> 6, n = i & 63;
        tile[n*66 + d] = fb[(long)d*NN + n0 + n];
    }

    const float inv = rsqrtf(1.0f + 1e-5f);
    const float s2 = g2[lane]*inv, bb2 = b2[lane];
    const float s3 = g3[lane]*inv;
    unsigned long long w2p[32], w3ap[16];
    #pragma unroll
    for (int c = 0; c < 32; c++)
        w2p[c] = pack2(W2[lane*64 + 2*c]*s2, W2[lane*64 + 2*c + 1]*s2);
    #pragma unroll
    for (int c = 0; c < 16; c++)
        w3ap[c] = pack2(W3[lane*64 + 2*c]*s3, W3[lane*64 + 2*c + 1]*s3);
    __syncthreads();

    #pragma unroll 1
    for (int j = 0; j < 8; j++){
        const int n = wid*8 + j;
        const unsigned long long* xp = (const unsigned long long*)(tile + n*66);
        unsigned long long a0=0ull, a1=0ull, a2=0ull, a3=0ull;
        #pragma unroll
        for (int c = 0; c < 32; c += 4){
            a0 = fma2(w2p[c+0], xp[c+0], a0);
            a1 = fma2(w2p[c+1], xp[c+1], a1);
            a2 = fma2(w2p[c+2], xp[c+2], a2);
            a3 = fma2(w2p[c+3], xp[c+3], a3);
        }
        float l0,h0,l1,h1,l2,h2,l3,h3;
        unpack2(a0,l0,h0); unpack2(a1,l1,h1); unpack2(a2,l2,h2); unpack2(a3,l3,h3);
        float f = fmaxf((l0+h0)+(l1+h1)+(l2+h2)+(l3+h3) + bb2, 0.0f);

        const long p = (long)b*NN + n0 + n;
        hs[wid][lane] = f;
        g_f[p*32 + lane] = f;
        __syncwarp();

        const unsigned long long* hp = (const unsigned long long*)hs[wid];
        unsigned long long z0=0ull, z1=0ull, z2=0ull, z3=0ull;
        #pragma unroll
        for (int c = 0; c < 16; c += 4){
            z0 = fma2(w3ap[c+0], hp[c+0], z0);
            z1 = fma2(w3ap[c+1], hp[c+1], z1);
            z2 = fma2(w3ap[c+2], hp[c+2], z2);
            z3 = fma2(w3ap[c+3], hp[c+3], z3);
        }
        unpack2(z0,l0,h0); unpack2(z1,l1,h1); unpack2(z2,l2,h2); unpack2(z3,l3,h3);
        g_z[p*32 + lane] = (l0+h0)+(l1+h1)+(l2+h2)+(l3+h3);
        __syncwarp();
    }
}

// ---------------------------------------------------------------------------
// Kernel B: one warp per point. Per neighbor: h1 = relu(s1*(W1@u)+b1),
// y = z_neighbor + (s3*W3b)@h1 + b3, maxpool; epilogue W4 over [max; fself].
__global__ void __launch_bounds__(256) kernelB(
    const float* __restrict__ xyz, const int* __restrict__ neigh32,
    const float* __restrict__ W1, const float* __restrict__ g1, const float* __restrict__ b1,
    const float* __restrict__ W3, const float* __restrict__ g3, const float* __restrict__ b3,
    const float* __restrict__ W4, const float* __restrict__ g4, const float* __restrict__ b4,
    float* __restrict__ out)
{
    __shared__ __align__(8) unsigned long long sW4[32*64];  // [c_pair][o], scale folded
    __shared__ float sB4[64];
    __shared__ __align__(8) float sH[8][2][32];             // double-buffered h1
    __shared__ __align__(8) float sE[8][64];                // epilogue operand
    __shared__ float sOut[64][9];

    const int tid  = threadIdx.x;
    const int lane = tid & 31;
    const int wid  = tid >> 5;
    const float inv = rsqrtf(1.0f + 1e-5f);

    for (int i = tid; i < 2048; i += 256){
        int c2 = i >> 6, o = i & 63;
        float2 wv = ((const float2*)W4)[o*32 + c2];
        float s4 = g4[o] * inv;
        sW4[i] = pack2(wv.x*s4, wv.y*s4);
    }
    if (tid < 64) sB4[tid] = b4[tid];

    const float s1 = g1[lane]*inv, bb1 = b1[lane];
    const float s3 = g3[lane]*inv, bb3 = b3[lane];
    unsigned long long w1p[5];
    #pragma unroll
    for (int c = 0; c < 5; c++)
        w1p[c] = pack2(W1[lane*10 + 2*c]*s1, W1[lane*10 + 2*c + 1]*s1);
    unsigned long long w3bp[16];
    #pragma unroll
    for (int c = 0; c < 16; c++)
        w3bp[c] = pack2(W3[lane*64 + 32 + 2*c]*s3, W3[lane*64 + 33 + 2*c]*s3);

    const int is64 = g_is64;
    __syncthreads();

    const int grp = blockIdx.x;
    const int p = grp*8 + wid;
    const int b = p / NN, n = p - b*NN;
    const float* xb = xyz + (long)b*NN*3;
    const float Px = xb[n*3+0], Py = xb[n*3+1], Pz = xb[n*3+2];
    const float fself = g_f[(long)p*32 + lane];
    const float* zb = g_z + (long)b*NN*32;

    int myidx = 0;
    if (lane < 16) myidx = is64 ? neigh32[2*(p*16 + lane)] : neigh32[p*16 + lane];

    int idx_c = __shfl_sync(0xffffffffu, myidx, 0);
    float zc   = zb[idx_c*32 + lane];
    float Qx_c = xb[idx_c*3+0], Qy_c = xb[idx_c*3+1], Qz_c = xb[idx_c*3+2];
    float maxv = -3.4e38f;

    #pragma unroll 1
    for (int k = 0; k < 16; k++){
        int kn = (k+1 < 16) ? k+1 : k;
        int idx_n = __shfl_sync(0xffffffffu, myidx, kn);
        float zn   = zb[idx_n*32 + lane];
        float Qx_n = xb[idx_n*3+0], Qy_n = xb[idx_n*3+1], Qz_n = xb[idx_n*3+2];

        float rx = Px - Qx_c, ry = Py - Qy_c, rz = Pz - Qz_c;
        float dist = sqrtf(rx*rx + ry*ry + rz*rz);

        unsigned long long a0 = 0ull, a1 = 0ull;
        a0 = fma2(w1p[0], pack2(dist, rx), a0);
        a1 = fma2(w1p[1], pack2(ry,  rz), a1);
        a0 = fma2(w1p[2], pack2(Px,  Py), a0);
        a1 = fma2(w1p[3], pack2(Pz,  Qx_c), a1);
        a0 = fma2(w1p[4], pack2(Qy_c, Qz_c), a0);
        float lo0, hi0, lo1, hi1;
        unpack2(a0, lo0, hi0); unpack2(a1, lo1, hi1);
        float h1 = fmaxf((lo0+hi0)+(lo1+hi1) + bb1, 0.0f);

        float* hbuf = sH[wid][k & 1];
        hbuf[lane] = h1;
        __syncwarp();
        const unsigned long long* hp = (const unsigned long long*)hbuf;
        unsigned long long c0=0ull, c1=0ull, c2=0ull, c3=0ull;
        #pragma unroll
        for (int c = 0; c < 16; c += 4){
            c0 = fma2(w3bp[c+0], hp[c+0], c0);
            c1 = fma2(w3bp[c+1], hp[c+1], c1);
            c2 = fma2(w3bp[c+2], hp[c+2], c2);
            c3 = fma2(w3bp[c+3], hp[c+3], c3);
        }
        float l0,h0,l1,h1v,l2,h2,l3,h3;
        unpack2(c0,l0,h0); unpack2(c1,l1,h1v); unpack2(c2,l2,h2); unpack2(c3,l3,h3);
        float y = zc + (l0+h0)+(l1+h1v)+(l2+h2)+(l3+h3) + bb3;
        maxv = fmaxf(maxv, y);

        zc = zn; Qx_c = Qx_n; Qy_c = Qy_n; Qz_c = Qz_n;
    }
    maxv = fmaxf(maxv, 0.0f);   // relu commutes with max

    sE[wid][lane]      = maxv;
    sE[wid][32 + lane] = fself;
    __syncwarp();
    const unsigned long long* ep = (const unsigned long long*)sE[wid];
    unsigned long long e0a=0ull, e0b=0ull, e1a=0ull, e1b=0ull;
    #pragma unroll
    for (int c = 0; c < 32; c += 2){
        unsigned long long xv0 = ep[c], xv1 = ep[c+1];
        e0a = fma2(sW4[(c+0)*64 + lane],      xv0, e0a);
        e0b = fma2(sW4[(c+1)*64 + lane],      xv1, e0b);
        e1a = fma2(sW4[(c+0)*64 + lane + 32], xv0, e1a);
        e1b = fma2(sW4[(c+1)*64 + lane + 32], xv1, e1b);
    }
    float l0,h0,l1,h1v,l2,h2,l3,h3;
    unpack2(e0a,l0,h0); unpack2(e0b,l1,h1v); unpack2(e1a,l2,h2); unpack2(e1b,l3,h3);
    float o0 = fmaxf(sB4[lane]      + (l0+h0)+(l1+h1v), 0.0f);
    float o1 = fmaxf(sB4[lane + 32] + (l2+h2)+(l3+h3),  0.0f);
    __syncwarp();

    sOut[lane][wid]      = o0;
    sOut[lane + 32][wid] = o1;
    __syncthreads();
    for (int i = tid; i < 512; i += 256){
        int o = i >> 3, j = i & 7;
        int pp = grp*8 + j;
        int b2_ = pp / NN, n2_ = pp - b2_*NN;
        out[((long)b2_*64 + o)*NN + n2_] = sOut[o][j];
    }
}

// ---------------------------------------------------------------------------
extern "C" void kernel_launch(void* const* d_in, const int* in_sizes, int n_in,
                              void* d_out, int out_size)
{
    const float *feature=0, *xyzp=0, *W1=0, *W2=0, *W3=0, *W4=0;
    const void* neigh=0;
    const float* s32[6] = {0,0,0,0,0,0};   // g1,b1,g2,b2,g3,b3 (encounter order)
    const float* s64[2] = {0,0};           // g4,b4
    int n2048 = 0, c32 = 0, c64 = 0;
    for (int i = 0; i < n_in; i++){
        int sz = in_sizes[i];
        const float* p = (const float*)d_in[i];
        if      (sz == 10485760) feature = p;
        else if (sz == 491520)   xyzp = p;
        else if (sz == 2621440)  neigh = d_in[i];
        else if (sz == 320)      W1 = p;
        else if (sz == 2048)     { if (n2048++ == 0) W2 = p; else W3 = p; }
        else if (sz == 4096)     W4 = p;
        else if (sz == 32)       { if (c32 < 6) s32[c32++] = p; }
        else if (sz == 64)       { if (c64 < 2) s64[c64++] = p; }
    }

    detect_idx_kernel<<<1, 32>>>((const int*)neigh);
    kernelA<<<2560, 256>>>(feature, W2, s32[2], s32[3], W3, s32[4]);
    kernelB<<<PT/8, 256>>>(xyzp, (const int*)neigh,
                           W1, s32[0], s32[1],
                           W3, s32[4], s32[5],
                           W4, s64[0], s64[1],
                           (float*)d_out);
}

// round 3
// speedup vs baseline: 1.9948x; 1.9948x over previous
#include <cuda_runtime.h>

#define NN 40960
#define PT (4*NN)

__device__ float g_f[(long)PT*32];   // f = relu(s2*(W2@feat)+b2), [point][32]
__device__ float g_z[(long)PT*32];   // z = s3 * (W3a @ f), [point][32]
__device__ int g_is64;

__device__ __forceinline__ unsigned long long pack2(float lo, float hi){
    unsigned long long r;
    asm("mov.b64 %0, {%1, %2};" : "=l"(r) : "f"(lo), "f"(hi));
    return r;
}
__device__ __forceinline__ void unpack2(unsigned long long v, float& lo, float& hi){
    asm("mov.b64 {%0, %1}, %2;" : "=f"(lo), "=f"(hi) : "l"(v));
}
__device__ __forceinline__ unsigned long long fma2(unsigned long long a, unsigned long long b, unsigned long long c){
    unsigned long long d;
    asm("fma.rn.f32x2 %0, %1, %2, %3;" : "=l"(d) : "l"(a), "l"(b), "l"(c));
    return d;
}

// ---------------------------------------------------------------------------
__global__ void detect_idx_kernel(const int* __restrict__ neigh32){
    if (threadIdx.x == 0){
        int allzero = 1;
        #pragma unroll 1
        for (int i = 0; i < 128; i++)
            if (neigh32[2*i + 1] != 0) { allzero = 0; break; }
        g_is64 = allzero;
    }
}

// ---------------------------------------------------------------------------
// Kernel A: per point  f = relu(s2*(W2@x)+b2);  z = s3*(W3a@f)
__global__ void __launch_bounds__(256) kernelA(
    const float* __restrict__ feat,
    const float* __restrict__ W2, const float* __restrict__ g2, const float* __restrict__ b2,
    const float* __restrict__ W3, const float* __restrict__ g3)
{
    __shared__ __align__(8) float tile[64*66];   // [n][d], pad 66
    __shared__ __align__(8) float hs[8][32];

    const int tid  = threadIdx.x;
    const int lane = tid & 31;
    const int wid  = tid >> 5;

    const float inv = rsqrtf(1.0f + 1e-5f);
    const float s2 = g2[lane]*inv, bb2 = b2[lane];
    const float s3 = g3[lane]*inv;
    unsigned long long w2p[32], w3ap[16];
    #pragma unroll
    for (int c = 0; c < 32; c++)
        w2p[c] = pack2(W2[lane*64 + 2*c]*s2, W2[lane*64 + 2*c + 1]*s2);
    #pragma unroll
    for (int c = 0; c < 16; c++)
        w3ap[c] = pack2(W3[lane*64 + 2*c]*s3, W3[lane*64 + 2*c + 1]*s3);

    #pragma unroll 1
    for (int blk = blockIdx.x; blk < 2560; blk += gridDim.x){
        const int b  = blk / 640;
        const int n0 = (blk - b*640) * 64;
        const float* fb = feat + (long)b*64*NN;
        __syncthreads();
        for (int i = tid; i < 4096; i += 256){
            int d = i >> 6, n = i & 63;
            tile[n*66 + d] = fb[(long)d*NN + n0 + n];
        }
        __syncthreads();

        #pragma unroll 1
        for (int j = 0; j < 8; j++){
            const int n = wid*8 + j;
            const unsigned long long* xp = (const unsigned long long*)(tile + n*66);
            unsigned long long a0=0ull, a1=0ull, a2=0ull, a3=0ull;
            #pragma unroll
            for (int c = 0; c < 32; c += 4){
                a0 = fma2(w2p[c+0], xp[c+0], a0);
                a1 = fma2(w2p[c+1], xp[c+1], a1);
                a2 = fma2(w2p[c+2], xp[c+2], a2);
                a3 = fma2(w2p[c+3], xp[c+3], a3);
            }
            float l0,h0,l1,h1,l2,h2,l3,h3;
            unpack2(a0,l0,h0); unpack2(a1,l1,h1); unpack2(a2,l2,h2); unpack2(a3,l3,h3);
            float f = fmaxf((l0+h0)+(l1+h1)+(l2+h2)+(l3+h3) + bb2, 0.0f);

            const long p = (long)b*NN + n0 + n;
            hs[wid][lane] = f;
            g_f[p*32 + lane] = f;
            __syncwarp();

            const unsigned long long* hp = (const unsigned long long*)hs[wid];
            unsigned long long z0=0ull, z1=0ull, z2=0ull, z3=0ull;
            #pragma unroll
            for (int c = 0; c < 16; c += 4){
                z0 = fma2(w3ap[c+0], hp[c+0], z0);
                z1 = fma2(w3ap[c+1], hp[c+1], z1);
                z2 = fma2(w3ap[c+2], hp[c+2], z2);
                z3 = fma2(w3ap[c+3], hp[c+3], z3);
            }
            unpack2(z0,l0,h0); unpack2(z1,l1,h1); unpack2(z2,l2,h2); unpack2(z3,l3,h3);
            g_z[p*32 + lane] = (l0+h0)+(l1+h1)+(l2+h2)+(l3+h3);
            __syncwarp();
        }
    }
}

// ---------------------------------------------------------------------------
// Kernel B: persistent; one warp per point per group. Per neighbor:
// h1 = relu(s1*(W1@u)+b1); y = z_neigh + (s3*W3b)@h1 + b3; maxpool.
// Epilogue: out = relu(s4*(W4@[max; fself]) + b4), staged coalesced store.
__global__ void __launch_bounds__(256) kernelB(
    const float* __restrict__ xyz, const int* __restrict__ neigh32,
    const float* __restrict__ W1, const float* __restrict__ g1, const float* __restrict__ b1,
    const float* __restrict__ W3, const float* __restrict__ g3, const float* __restrict__ b3,
    const float* __restrict__ W4, const float* __restrict__ g4, const float* __restrict__ b4,
    float* __restrict__ out)
{
    __shared__ __align__(8) unsigned long long sW4[32*64];  // [c_pair][o], scale folded
    __shared__ float sB4[64];
    __shared__ __align__(8) float sH[8][2][32];             // double-buffered h1
    __shared__ __align__(8) float sE[8][64];                // epilogue operand
    __shared__ float sOut[64][9];

    const int tid  = threadIdx.x;
    const int lane = tid & 31;
    const int wid  = tid >> 5;
    const float inv = rsqrtf(1.0f + 1e-5f);

    for (int i = tid; i < 2048; i += 256){
        int c2 = i >> 6, o = i & 63;
        float2 wv = ((const float2*)W4)[o*32 + c2];
        float s4 = g4[o] * inv;
        sW4[i] = pack2(wv.x*s4, wv.y*s4);
    }
    if (tid < 64) sB4[tid] = b4[tid];

    const float s1 = g1[lane]*inv, bb1 = b1[lane];
    const float s3 = g3[lane]*inv, bb3 = b3[lane];
    unsigned long long w1p[5];
    #pragma unroll
    for (int c = 0; c < 5; c++)
        w1p[c] = pack2(W1[lane*10 + 2*c]*s1, W1[lane*10 + 2*c + 1]*s1);
    unsigned long long w3bp[16];
    #pragma unroll
    for (int c = 0; c < 16; c++)
        w3bp[c] = pack2(W3[lane*64 + 32 + 2*c]*s3, W3[lane*64 + 33 + 2*c]*s3);

    const int is64 = g_is64;
    __syncthreads();

    #pragma unroll 1
    for (int grp = blockIdx.x; grp < PT/8; grp += gridDim.x){
        const int p = grp*8 + wid;
        const int b = p / NN, n = p - b*NN;
        const float* xb = xyz + (long)b*NN*3;
        const float Px = xb[n*3+0], Py = xb[n*3+1], Pz = xb[n*3+2];
        const float fself = g_f[(long)p*32 + lane];
        const float* zb = g_z + (long)b*NN*32;

        int myidx = 0;
        if (lane < 16) myidx = is64 ? neigh32[2*(p*16 + lane)] : neigh32[p*16 + lane];

        int idx_c = __shfl_sync(0xffffffffu, myidx, 0);
        float zc   = zb[idx_c*32 + lane];
        float Qx_c = xb[idx_c*3+0], Qy_c = xb[idx_c*3+1], Qz_c = xb[idx_c*3+2];
        float maxv = -3.4e38f;

        #pragma unroll 1
        for (int k = 0; k < 16; k++){
            int kn = (k+1 < 16) ? k+1 : k;
            int idx_n = __shfl_sync(0xffffffffu, myidx, kn);
            float zn   = zb[idx_n*32 + lane];
            float Qx_n = xb[idx_n*3+0], Qy_n = xb[idx_n*3+1], Qz_n = xb[idx_n*3+2];

            float rx = Px - Qx_c, ry = Py - Qy_c, rz = Pz - Qz_c;
            float dist = sqrtf(rx*rx + ry*ry + rz*rz);

            unsigned long long a0 = 0ull, a1 = 0ull;
            a0 = fma2(w1p[0], pack2(dist, rx), a0);
            a1 = fma2(w1p[1], pack2(ry,  rz), a1);
            a0 = fma2(w1p[2], pack2(Px,  Py), a0);
            a1 = fma2(w1p[3], pack2(Pz,  Qx_c), a1);
            a0 = fma2(w1p[4], pack2(Qy_c, Qz_c), a0);
            float lo0, hi0, lo1, hi1;
            unpack2(a0, lo0, hi0); unpack2(a1, lo1, hi1);
            float h1 = fmaxf((lo0+hi0)+(lo1+hi1) + bb1, 0.0f);

            float* hbuf = sH[wid][k & 1];
            hbuf[lane] = h1;
            __syncwarp();
            const unsigned long long* hp = (const unsigned long long*)hbuf;
            unsigned long long c0=0ull, c1=0ull, c2=0ull, c3=0ull;
            #pragma unroll
            for (int c = 0; c < 16; c += 4){
                c0 = fma2(w3bp[c+0], hp[c+0], c0);
                c1 = fma2(w3bp[c+1], hp[c+1], c1);
                c2 = fma2(w3bp[c+2], hp[c+2], c2);
                c3 = fma2(w3bp[c+3], hp[c+3], c3);
            }
            float l0,h0,l1,h1v,l2,h2,l3,h3;
            unpack2(c0,l0,h0); unpack2(c1,l1,h1v); unpack2(c2,l2,h2); unpack2(c3,l3,h3);
            float y = zc + (l0+h0)+(l1+h1v)+(l2+h2)+(l3+h3) + bb3;
            maxv = fmaxf(maxv, y);

            zc = zn; Qx_c = Qx_n; Qy_c = Qy_n; Qz_c = Qz_n;
        }
        maxv = fmaxf(maxv, 0.0f);   // relu commutes with max

        sE[wid][lane]      = maxv;
        sE[wid][32 + lane] = fself;
        __syncwarp();
        const unsigned long long* ep = (const unsigned long long*)sE[wid];
        unsigned long long e0a=0ull, e0b=0ull, e1a=0ull, e1b=0ull;
        #pragma unroll
        for (int c = 0; c < 32; c += 2){
            unsigned long long xv0 = ep[c], xv1 = ep[c+1];
            e0a = fma2(sW4[(c+0)*64 + lane],      xv0, e0a);
            e0b = fma2(sW4[(c+1)*64 + lane],      xv1, e0b);
            e1a = fma2(sW4[(c+0)*64 + lane + 32], xv0, e1a);
            e1b = fma2(sW4[(c+1)*64 + lane + 32], xv1, e1b);
        }
        float l0,h0,l1,h1v,l2,h2,l3,h3;
        unpack2(e0a,l0,h0); unpack2(e0b,l1,h1v); unpack2(e1a,l2,h2); unpack2(e1b,l3,h3);
        float o0 = fmaxf(sB4[lane]      + (l0+h0)+(l1+h1v), 0.0f);
        float o1 = fmaxf(sB4[lane + 32] + (l2+h2)+(l3+h3),  0.0f);
        __syncwarp();

        sOut[lane][wid]      = o0;
        sOut[lane + 32][wid] = o1;
        __syncthreads();
        for (int i = tid; i < 512; i += 256){
            int o = i >> 3, j = i & 7;
            int pp = grp*8 + j;
            int b2_ = pp / NN, n2_ = pp - b2_*NN;
            out[((long)b2_*64 + o)*NN + n2_] = sOut[o][j];
        }
        __syncthreads();
    }
}

// ---------------------------------------------------------------------------
extern "C" void kernel_launch(void* const* d_in, const int* in_sizes, int n_in,
                              void* d_out, int out_size)
{
    const float *feature=0, *xyzp=0, *W1=0, *W2=0, *W3=0, *W4=0;
    const void* neigh=0;
    const float* s32[6] = {0,0,0,0,0,0};   // g1,b1,g2,b2,g3,b3 (encounter order)
    const float* s64[2] = {0,0};           // g4,b4
    int n2048 = 0, c32 = 0, c64 = 0;
    for (int i = 0; i < n_in; i++){
        int sz = in_sizes[i];
        const float* p = (const float*)d_in[i];
        if      (sz == 10485760) feature = p;
        else if (sz == 491520)   xyzp = p;
        else if (sz == 2621440)  neigh = d_in[i];
        else if (sz == 320)      W1 = p;
        else if (sz == 2048)     { if (n2048++ == 0) W2 = p; else W3 = p; }
        else if (sz == 4096)     W4 = p;
        else if (sz == 32)       { if (c32 < 6) s32[c32++] = p; }
        else if (sz == 64)       { if (c64 < 2) s64[c64++] = p; }
    }

    detect_idx_kernel<<<1, 32>>>((const int*)neigh);
    kernelA<<<1184, 256>>>(feature, W2, s32[2], s32[3], W3, s32[4]);
    kernelB<<<592, 256>>>(xyzp, (const int*)neigh,
                          W1, s32[0], s32[1],
                          W3, s32[4], s32[5],
                          W4, s64[0], s64[1],
                          (float*)d_out);
}

// round 4
// speedup vs baseline: 2.1757x; 1.0906x over previous
#include <cuda_runtime.h>

#define NN 40960
#define PT (4*NN)

__device__ float g_f[(long)PT*32];   // f = relu(s2*(W2@feat)+b2), [point][32]
__device__ float g_z[(long)PT*32];   // z = s3 * (W3a @ f), [point][32]
__device__ int g_is64;

__device__ __forceinline__ unsigned long long pack2(float lo, float hi){
    unsigned long long r;
    asm("mov.b64 %0, {%1, %2};" : "=l"(r) : "f"(lo), "f"(hi));
    return r;
}
__device__ __forceinline__ void unpack2(unsigned long long v, float& lo, float& hi){
    asm("mov.b64 {%0, %1}, %2;" : "=f"(lo), "=f"(hi) : "l"(v));
}
__device__ __forceinline__ unsigned long long fma2(unsigned long long a, unsigned long long b, unsigned long long c){
    unsigned long long d;
    asm("fma.rn.f32x2 %0, %1, %2, %3;" : "=l"(d) : "l"(a), "l"(b), "l"(c));
    return d;
}

// ---------------------------------------------------------------------------
// Kernel A: per point  f = relu(s2*(W2@x)+b2);  z = s3*(W3a@f)
// Block 0 / thread 0 also detects neigh_idx dtype (int64 vs int32).
__global__ void __launch_bounds__(256) kernelA(
    const float* __restrict__ feat,
    const float* __restrict__ W2, const float* __restrict__ g2, const float* __restrict__ b2,
    const float* __restrict__ W3, const float* __restrict__ g3,
    const int* __restrict__ neigh32)
{
    __shared__ __align__(8) float tile[64*66];   // [n][d], pad 66
    __shared__ __align__(8) float hs[8][32];

    const int tid  = threadIdx.x;
    const int lane = tid & 31;
    const int wid  = tid >> 5;

    if (blockIdx.x == 0 && tid == 0){
        int allzero = 1;
        #pragma unroll 1
        for (int i = 0; i < 128; i++)
            if (neigh32[2*i + 1] != 0) { allzero = 0; break; }
        g_is64 = allzero;
    }

    const float inv = rsqrtf(1.0f + 1e-5f);
    const float s2 = g2[lane]*inv, bb2 = b2[lane];
    const float s3 = g3[lane]*inv;
    unsigned long long w2p[32], w3ap[16];
    #pragma unroll
    for (int c = 0; c < 32; c++)
        w2p[c] = pack2(W2[lane*64 + 2*c]*s2, W2[lane*64 + 2*c + 1]*s2);
    #pragma unroll
    for (int c = 0; c < 16; c++)
        w3ap[c] = pack2(W3[lane*64 + 2*c]*s3, W3[lane*64 + 2*c + 1]*s3);

    #pragma unroll 1
    for (int blk = blockIdx.x; blk < 2560; blk += gridDim.x){
        const int b  = blk / 640;
        const int n0 = (blk - b*640) * 64;
        const float* fb = feat + (long)b*64*NN;
        __syncthreads();
        for (int i = tid; i < 4096; i += 256){
            int d = i >> 6, n = i & 63;
            tile[n*66 + d] = fb[(long)d*NN + n0 + n];
        }
        __syncthreads();

        #pragma unroll 1
        for (int j = 0; j < 8; j++){
            const int n = wid*8 + j;
            const unsigned long long* xp = (const unsigned long long*)(tile + n*66);
            unsigned long long a0=0ull, a1=0ull, a2=0ull, a3=0ull;
            #pragma unroll
            for (int c = 0; c < 32; c += 4){
                a0 = fma2(w2p[c+0], xp[c+0], a0);
                a1 = fma2(w2p[c+1], xp[c+1], a1);
                a2 = fma2(w2p[c+2], xp[c+2], a2);
                a3 = fma2(w2p[c+3], xp[c+3], a3);
            }
            float l0,h0,l1,h1,l2,h2,l3,h3;
            unpack2(a0,l0,h0); unpack2(a1,l1,h1); unpack2(a2,l2,h2); unpack2(a3,l3,h3);
            float f = fmaxf((l0+h0)+(l1+h1)+(l2+h2)+(l3+h3) + bb2, 0.0f);

            const long p = (long)b*NN + n0 + n;
            hs[wid][lane] = f;
            g_f[p*32 + lane] = f;
            __syncwarp();

            const unsigned long long* hp = (const unsigned long long*)hs[wid];
            unsigned long long z0=0ull, z1=0ull, z2=0ull, z3=0ull;
            #pragma unroll
            for (int c = 0; c < 16; c += 4){
                z0 = fma2(w3ap[c+0], hp[c+0], z0);
                z1 = fma2(w3ap[c+1], hp[c+1], z1);
                z2 = fma2(w3ap[c+2], hp[c+2], z2);
                z3 = fma2(w3ap[c+3], hp[c+3], z3);
            }
            unpack2(z0,l0,h0); unpack2(z1,l1,h1); unpack2(z2,l2,h2); unpack2(z3,l3,h3);
            g_z[p*32 + lane] = (l0+h0)+(l1+h1)+(l2+h2)+(l3+h3);
            __syncwarp();
        }
    }
}

// ---------------------------------------------------------------------------
// Kernel B: persistent, one warp per point. All neighbor gathers (xyz per-lane,
// z as MLP=16 batch) issued up front; inner loop is pure FMA/SHFL/LDS.
__global__ void __launch_bounds__(256, 2) kernelB(
    const float* __restrict__ xyz, const int* __restrict__ neigh32,
    const float* __restrict__ W1, const float* __restrict__ g1, const float* __restrict__ b1,
    const float* __restrict__ W3, const float* __restrict__ g3, const float* __restrict__ b3,
    const float* __restrict__ W4, const float* __restrict__ g4, const float* __restrict__ b4,
    float* __restrict__ out)
{
    __shared__ __align__(8) unsigned long long sW4[32*64];  // [c_pair][o], scale folded
    __shared__ float sB4[64];
    __shared__ __align__(8) float sH[8][2][32];             // double-buffered h1
    __shared__ __align__(8) float sE[8][64];                // epilogue operand
    __shared__ float sOut[64][9];

    const int tid  = threadIdx.x;
    const int lane = tid & 31;
    const int wid  = tid >> 5;
    const float inv = rsqrtf(1.0f + 1e-5f);

    for (int i = tid; i < 2048; i += 256){
        int c2 = i >> 6, o = i & 63;
        float2 wv = ((const float2*)W4)[o*32 + c2];
        float s4 = g4[o] * inv;
        sW4[i] = pack2(wv.x*s4, wv.y*s4);
    }
    if (tid < 64) sB4[tid] = b4[tid];

    const float s1 = g1[lane]*inv, bb1 = b1[lane];
    const float s3 = g3[lane]*inv, bb3 = b3[lane];
    unsigned long long w1p[5];
    #pragma unroll
    for (int c = 0; c < 5; c++)
        w1p[c] = pack2(W1[lane*10 + 2*c]*s1, W1[lane*10 + 2*c + 1]*s1);
    unsigned long long w3bp[16];
    #pragma unroll
    for (int c = 0; c < 16; c++)
        w3bp[c] = pack2(W3[lane*64 + 32 + 2*c]*s3, W3[lane*64 + 33 + 2*c]*s3);

    const int is64 = g_is64;
    __syncthreads();

    #pragma unroll 1
    for (int grp = blockIdx.x; grp < PT/8; grp += gridDim.x){
        const int p = grp*8 + wid;
        const int b = p / NN, n = p - b*NN;
        const float* xb = xyz + (long)b*NN*3;
        const float* zb = g_z + (long)b*NN*32;
        const float Px = xb[n*3+0], Py = xb[n*3+1], Pz = xb[n*3+2];
        const float fself = g_f[(long)p*32 + lane];

        // lane j<16 owns neighbor j: its index and xyz
        int myidx = 0;
        if (lane < 16) myidx = is64 ? neigh32[2*(p*16 + lane)] : neigh32[p*16 + lane];
        float Qx = 0.f, Qy = 0.f, Qz = 0.f;
        if (lane < 16){
            Qx = xb[myidx*3+0]; Qy = xb[myidx*3+1]; Qz = xb[myidx*3+2];
        }

        // batched z gathers: MLP=16, no memory ops in the compute loop
        float zk[16];
        #pragma unroll
        for (int k = 0; k < 16; k++){
            int id = __shfl_sync(0xffffffffu, myidx, k);
            zk[k] = zb[id*32 + lane];
        }

        float maxv = -3.4e38f;
        #pragma unroll
        for (int k = 0; k < 16; k++){
            float Qxk = __shfl_sync(0xffffffffu, Qx, k);
            float Qyk = __shfl_sync(0xffffffffu, Qy, k);
            float Qzk = __shfl_sync(0xffffffffu, Qz, k);
            float rx = Px - Qxk, ry = Py - Qyk, rz = Pz - Qzk;
            float dist = sqrtf(rx*rx + ry*ry + rz*rz);

            unsigned long long a0 = 0ull, a1 = 0ull;
            a0 = fma2(w1p[0], pack2(dist, rx), a0);
            a1 = fma2(w1p[1], pack2(ry,  rz), a1);
            a0 = fma2(w1p[2], pack2(Px,  Py), a0);
            a1 = fma2(w1p[3], pack2(Pz,  Qxk), a1);
            a0 = fma2(w1p[4], pack2(Qyk, Qzk), a0);
            float lo0, hi0, lo1, hi1;
            unpack2(a0, lo0, hi0); unpack2(a1, lo1, hi1);
            float h1 = fmaxf((lo0+hi0)+(lo1+hi1) + bb1, 0.0f);

            float* hbuf = sH[wid][k & 1];
            hbuf[lane] = h1;
            __syncwarp();
            const unsigned long long* hp = (const unsigned long long*)hbuf;
            unsigned long long c0=0ull, c1=0ull, c2=0ull, c3=0ull;
            #pragma unroll
            for (int c = 0; c < 16; c += 4){
                c0 = fma2(w3bp[c+0], hp[c+0], c0);
                c1 = fma2(w3bp[c+1], hp[c+1], c1);
                c2 = fma2(w3bp[c+2], hp[c+2], c2);
                c3 = fma2(w3bp[c+3], hp[c+3], c3);
            }
            float l0,h0,l1,h1v,l2,h2,l3,h3;
            unpack2(c0,l0,h0); unpack2(c1,l1,h1v); unpack2(c2,l2,h2); unpack2(c3,l3,h3);
            float y = zk[k] + (l0+h0)+(l1+h1v)+(l2+h2)+(l3+h3) + bb3;
            maxv = fmaxf(maxv, y);
        }
        maxv = fmaxf(maxv, 0.0f);   // relu commutes with max

        sE[wid][lane]      = maxv;
        sE[wid][32 + lane] = fself;
        __syncwarp();
        const unsigned long long* ep = (const unsigned long long*)sE[wid];
        unsigned long long e0a=0ull, e0b=0ull, e1a=0ull, e1b=0ull;
        #pragma unroll
        for (int c = 0; c < 32; c += 2){
            unsigned long long xv0 = ep[c], xv1 = ep[c+1];
            e0a = fma2(sW4[(c+0)*64 + lane],      xv0, e0a);
            e0b = fma2(sW4[(c+1)*64 + lane],      xv1, e0b);
            e1a = fma2(sW4[(c+0)*64 + lane + 32], xv0, e1a);
            e1b = fma2(sW4[(c+1)*64 + lane + 32], xv1, e1b);
        }
        float l0,h0,l1,h1v,l2,h2,l3,h3;
        unpack2(e0a,l0,h0); unpack2(e0b,l1,h1v); unpack2(e1a,l2,h2); unpack2(e1b,l3,h3);
        float o0 = fmaxf(sB4[lane]      + (l0+h0)+(l1+h1v), 0.0f);
        float o1 = fmaxf(sB4[lane + 32] + (l2+h2)+(l3+h3),  0.0f);
        __syncwarp();

        sOut[lane][wid]      = o0;
        sOut[lane + 32][wid] = o1;
        __syncthreads();
        for (int i = tid; i < 512; i += 256){
            int o = i >> 3, j = i & 7;
            int pp = grp*8 + j;
            int b2_ = pp / NN, n2_ = pp - b2_*NN;
            out[((long)b2_*64 + o)*NN + n2_] = sOut[o][j];
        }
        __syncthreads();
    }
}

// ---------------------------------------------------------------------------
extern "C" void kernel_launch(void* const* d_in, const int* in_sizes, int n_in,
                              void* d_out, int out_size)
{
    const float *feature=0, *xyzp=0, *W1=0, *W2=0, *W3=0, *W4=0;
    const void* neigh=0;
    const float* s32[6] = {0,0,0,0,0,0};   // g1,b1,g2,b2,g3,b3 (encounter order)
    const float* s64[2] = {0,0};           // g4,b4
    int n2048 = 0, c32 = 0, c64 = 0;
    for (int i = 0; i < n_in; i++){
        int sz = in_sizes[i];
        const float* p = (const float*)d_in[i];
        if      (sz == 10485760) feature = p;
        else if (sz == 491520)   xyzp = p;
        else if (sz == 2621440)  neigh = d_in[i];
        else if (sz == 320)      W1 = p;
        else if (sz == 2048)     { if (n2048++ == 0) W2 = p; else W3 = p; }
        else if (sz == 4096)     W4 = p;
        else if (sz == 32)       { if (c32 < 6) s32[c32++] = p; }
        else if (sz == 64)       { if (c64 < 2) s64[c64++] = p; }
    }

    kernelA<<<1184, 256>>>(feature, W2, s32[2], s32[3], W3, s32[4], (const int*)neigh);
    kernelB<<<592, 256>>>(xyzp, (const int*)neigh,
                          W1, s32[0], s32[1],
                          W3, s32[4], s32[5],
                          W4, s64[0], s64[1],
                          (float*)d_out);
}

// round 5
// speedup vs baseline: 2.7247x; 1.2524x over previous
#include <cuda_runtime.h>

#define NN 40960
#define PT (4*NN)

__device__ float g_f[(long)PT*32];   // f = relu(s2*(W2@feat)+b2), [point][32]
__device__ float g_z[(long)PT*32];   // z = s3 * (W3a @ f), [point][32]
__device__ int g_is64;

__device__ __forceinline__ unsigned long long pack2(float lo, float hi){
    unsigned long long r;
    asm("mov.b64 %0, {%1, %2};" : "=l"(r) : "f"(lo), "f"(hi));
    return r;
}
__device__ __forceinline__ void unpack2(unsigned long long v, float& lo, float& hi){
    asm("mov.b64 {%0, %1}, %2;" : "=f"(lo), "=f"(hi) : "l"(v));
}
__device__ __forceinline__ unsigned long long fma2(unsigned long long a, unsigned long long b, unsigned long long c){
    unsigned long long d;
    asm("fma.rn.f32x2 %0, %1, %2, %3;" : "=l"(d) : "l"(a), "l"(b), "l"(c));
    return d;
}

// ---------------------------------------------------------------------------
// Kernel A: per point  f = relu(s2*(W2@x)+b2);  z = s3*(W3a@f)
__global__ void __launch_bounds__(256) kernelA(
    const float* __restrict__ feat,
    const float* __restrict__ W2, const float* __restrict__ g2, const float* __restrict__ b2,
    const float* __restrict__ W3, const float* __restrict__ g3,
    const int* __restrict__ neigh32)
{
    __shared__ __align__(16) float tile[64*68];      // [n][d] pitch 68 (16B rows)
    __shared__ __align__(16) float hs[8][2][32];     // double-buffered f

    const int tid  = threadIdx.x;
    const int lane = tid & 31;
    const int wid  = tid >> 5;

    if (blockIdx.x == 0 && tid == 0){
        int allzero = 1;
        #pragma unroll 1
        for (int i = 0; i < 128; i++)
            if (neigh32[2*i + 1] != 0) { allzero = 0; break; }
        g_is64 = allzero;
    }

    const float inv = rsqrtf(1.0f + 1e-5f);
    const float s2 = g2[lane]*inv, bb2 = b2[lane];
    const float s3 = g3[lane]*inv;

    // stage W2 coalesced into tile (pitch 66), read per-lane rows (2-way conflict)
    unsigned long long w2p[32], w3ap[16];
    for (int i = tid; i < 2048; i += 256) tile[(i>>6)*66 + (i&63)] = W2[i];
    __syncthreads();
    #pragma unroll
    for (int c = 0; c < 32; c++)
        w2p[c] = pack2(tile[lane*66 + 2*c]*s2, tile[lane*66 + 2*c + 1]*s2);
    __syncthreads();
    for (int i = tid; i < 2048; i += 256) tile[(i>>6)*66 + (i&63)] = W3[i];
    __syncthreads();
    #pragma unroll
    for (int c = 0; c < 16; c++)
        w3ap[c] = pack2(tile[lane*66 + 2*c]*s3, tile[lane*66 + 2*c + 1]*s3);

    #pragma unroll 1
    for (int blk = blockIdx.x; blk < 2560; blk += gridDim.x){
        const int b  = blk / 640;
        const int n0 = (blk - b*640) * 64;
        const float* fb = feat + (long)b*64*NN;
        __syncthreads();
        for (int i = tid; i < 4096; i += 256){
            int d = i >> 6, n = i & 63;
            tile[n*68 + d] = fb[(long)d*NN + n0 + n];
        }
        __syncthreads();

        #pragma unroll 1
        for (int j = 0; j < 8; j++){
            const int n = wid*8 + j;
            const float4* xp4 = (const float4*)(tile + n*68);
            unsigned long long a0=0ull, a1=0ull, a2=0ull, a3=0ull;
            #pragma unroll
            for (int c = 0; c < 16; c += 4){
                float4 v0 = xp4[c+0], v1 = xp4[c+1], v2 = xp4[c+2], v3 = xp4[c+3];
                a0 = fma2(w2p[2*c+0], pack2(v0.x,v0.y), a0);
                a1 = fma2(w2p[2*c+1], pack2(v0.z,v0.w), a1);
                a2 = fma2(w2p[2*c+2], pack2(v1.x,v1.y), a2);
                a3 = fma2(w2p[2*c+3], pack2(v1.z,v1.w), a3);
                a0 = fma2(w2p[2*c+4], pack2(v2.x,v2.y), a0);
                a1 = fma2(w2p[2*c+5], pack2(v2.z,v2.w), a1);
                a2 = fma2(w2p[2*c+6], pack2(v3.x,v3.y), a2);
                a3 = fma2(w2p[2*c+7], pack2(v3.z,v3.w), a3);
            }
            float l0,h0,l1,h1,l2,h2,l3,h3;
            unpack2(a0,l0,h0); unpack2(a1,l1,h1); unpack2(a2,l2,h2); unpack2(a3,l3,h3);
            float f = fmaxf((l0+h0)+(l1+h1)+(l2+h2)+(l3+h3) + bb2, 0.0f);

            const long p = (long)b*NN + n0 + n;
            float* hb = hs[wid][j & 1];
            hb[lane] = f;
            g_f[p*32 + lane] = f;
            __syncwarp();

            const float4* hp4 = (const float4*)hb;
            unsigned long long z0=0ull, z1=0ull, z2=0ull, z3=0ull;
            #pragma unroll
            for (int c = 0; c < 8; c += 4){
                float4 v0 = hp4[c+0], v1 = hp4[c+1], v2 = hp4[c+2], v3 = hp4[c+3];
                z0 = fma2(w3ap[2*c+0], pack2(v0.x,v0.y), z0);
                z1 = fma2(w3ap[2*c+1], pack2(v0.z,v0.w), z1);
                z2 = fma2(w3ap[2*c+2], pack2(v1.x,v1.y), z2);
                z3 = fma2(w3ap[2*c+3], pack2(v1.z,v1.w), z3);
                z0 = fma2(w3ap[2*c+4], pack2(v2.x,v2.y), z0);
                z1 = fma2(w3ap[2*c+5], pack2(v2.z,v2.w), z1);
                z2 = fma2(w3ap[2*c+6], pack2(v3.x,v3.y), z2);
                z3 = fma2(w3ap[2*c+7], pack2(v3.z,v3.w), z3);
            }
            unpack2(z0,l0,h0); unpack2(z1,l1,h1); unpack2(z2,l2,h2); unpack2(z3,l3,h3);
            g_z[p*32 + lane] = (l0+h0)+(l1+h1)+(l2+h2)+(l3+h3);
        }
    }
}

// ---------------------------------------------------------------------------
// Kernel B: persistent, one warp per point; LDS.128 operand reads.
__global__ void __launch_bounds__(256, 2) kernelB(
    const float* __restrict__ xyz, const int* __restrict__ neigh32,
    const float* __restrict__ W1, const float* __restrict__ g1, const float* __restrict__ b1,
    const float* __restrict__ W3, const float* __restrict__ g3, const float* __restrict__ b3,
    const float* __restrict__ W4, const float* __restrict__ g4, const float* __restrict__ b4,
    float* __restrict__ out)
{
    __shared__ __align__(16) unsigned long long sW4[32*64];  // [c_pair][o]
    __shared__ float sB4[64];
    __shared__ __align__(16) float sH[8][2][32];
    __shared__ __align__(16) float sE[8][64];
    __shared__ float sOut[64][9];

    const int tid  = threadIdx.x;
    const int lane = tid & 31;
    const int wid  = tid >> 5;
    const float inv = rsqrtf(1.0f + 1e-5f);

    const float s1 = g1[lane]*inv, bb1 = b1[lane];
    const float s3 = g3[lane]*inv, bb3 = b3[lane];
    unsigned long long w1p[5];
    #pragma unroll
    for (int c = 0; c < 5; c++)
        w1p[c] = pack2(W1[lane*10 + 2*c]*s1, W1[lane*10 + 2*c + 1]*s1);

    // stage W3 coalesced into sW4 region, read rows (pitch 66), then build sW4
    unsigned long long w3bp[16];
    {
        float* wt = (float*)sW4;
        for (int i = tid; i < 2048; i += 256) wt[(i>>6)*66 + (i&63)] = W3[i];
        __syncthreads();
        #pragma unroll
        for (int c = 0; c < 16; c++)
            w3bp[c] = pack2(wt[lane*66 + 32 + 2*c]*s3, wt[lane*66 + 33 + 2*c]*s3);
        __syncthreads();
    }
    for (int i = tid; i < 2048; i += 256){
        int c2 = i >> 6, o = i & 63;
        float2 wv = ((const float2*)W4)[o*32 + c2];
        float s4 = g4[o] * inv;
        sW4[i] = pack2(wv.x*s4, wv.y*s4);
    }
    if (tid < 64) sB4[tid] = b4[tid];

    const int is64 = g_is64;
    __syncthreads();

    #pragma unroll 1
    for (int grp = blockIdx.x; grp < PT/8; grp += gridDim.x){
        const int p = grp*8 + wid;
        const int b = p / NN, n = p - b*NN;
        const float* xb = xyz + (long)b*NN*3;
        const float* zb = g_z + (long)b*NN*32;
        const float Px = xb[n*3+0], Py = xb[n*3+1], Pz = xb[n*3+2];
        const float fself = g_f[(long)p*32 + lane];

        int myidx = 0;
        if (lane < 16) myidx = is64 ? neigh32[2*(p*16 + lane)] : neigh32[p*16 + lane];
        float Qx = 0.f, Qy = 0.f, Qz = 0.f;
        if (lane < 16){
            Qx = xb[myidx*3+0]; Qy = xb[myidx*3+1]; Qz = xb[myidx*3+2];
        }

        float zk[16];
        #pragma unroll
        for (int k = 0; k < 16; k++){
            int id = __shfl_sync(0xffffffffu, myidx, k);
            zk[k] = zb[id*32 + lane];
        }

        float maxv = -3.4e38f;
        #pragma unroll
        for (int k = 0; k < 16; k++){
            float Qxk = __shfl_sync(0xffffffffu, Qx, k);
            float Qyk = __shfl_sync(0xffffffffu, Qy, k);
            float Qzk = __shfl_sync(0xffffffffu, Qz, k);
            float rx = Px - Qxk, ry = Py - Qyk, rz = Pz - Qzk;
            float dist = sqrtf(rx*rx + ry*ry + rz*rz);

            unsigned long long a0 = 0ull, a1 = 0ull;
            a0 = fma2(w1p[0], pack2(dist, rx), a0);
            a1 = fma2(w1p[1], pack2(ry,  rz), a1);
            a0 = fma2(w1p[2], pack2(Px,  Py), a0);
            a1 = fma2(w1p[3], pack2(Pz,  Qxk), a1);
            a0 = fma2(w1p[4], pack2(Qyk, Qzk), a0);
            float lo0, hi0, lo1, hi1;
            unpack2(a0, lo0, hi0); unpack2(a1, lo1, hi1);
            float h1 = fmaxf((lo0+hi0)+(lo1+hi1) + bb1, 0.0f);

            float* hbuf = sH[wid][k & 1];
            hbuf[lane] = h1;
            __syncwarp();
            const float4* hp4 = (const float4*)hbuf;
            unsigned long long c0=0ull, c1=0ull, c2=0ull, c3=0ull;
            #pragma unroll
            for (int c = 0; c < 8; c += 4){
                float4 v0 = hp4[c+0], v1 = hp4[c+1], v2 = hp4[c+2], v3 = hp4[c+3];
                c0 = fma2(w3bp[2*c+0], pack2(v0.x,v0.y), c0);
                c1 = fma2(w3bp[2*c+1], pack2(v0.z,v0.w), c1);
                c2 = fma2(w3bp[2*c+2], pack2(v1.x,v1.y), c2);
                c3 = fma2(w3bp[2*c+3], pack2(v1.z,v1.w), c3);
                c0 = fma2(w3bp[2*c+4], pack2(v2.x,v2.y), c0);
                c1 = fma2(w3bp[2*c+5], pack2(v2.z,v2.w), c1);
                c2 = fma2(w3bp[2*c+6], pack2(v3.x,v3.y), c2);
                c3 = fma2(w3bp[2*c+7], pack2(v3.z,v3.w), c3);
            }
            float l0,h0,l1,h1v,l2,h2,l3,h3;
            unpack2(c0,l0,h0); unpack2(c1,l1,h1v); unpack2(c2,l2,h2); unpack2(c3,l3,h3);
            float y = zk[k] + (l0+h0)+(l1+h1v)+(l2+h2)+(l3+h3) + bb3;
            maxv = fmaxf(maxv, y);
        }
        maxv = fmaxf(maxv, 0.0f);   // relu commutes with max

        sE[wid][lane]      = maxv;
        sE[wid][32 + lane] = fself;
        __syncwarp();
        const float4* ep4 = (const float4*)sE[wid];
        unsigned long long e0a=0ull, e0b=0ull, e1a=0ull, e1b=0ull;
        #pragma unroll
        for (int c = 0; c < 16; c += 2){
            float4 v = ep4[c >> 1];
            unsigned long long xv0 = pack2(v.x, v.y), xv1 = pack2(v.z, v.w);
            e0a = fma2(sW4[(c+0)*64 + lane],      xv0, e0a);
            e0b = fma2(sW4[(c+1)*64 + lane],      xv1, e0b);
            e1a = fma2(sW4[(c+0)*64 + lane + 32], xv0, e1a);
            e1b = fma2(sW4[(c+1)*64 + lane + 32], xv1, e1b);
        }
        #pragma unroll
        for (int c = 16; c < 32; c += 2){
            float4 v = ep4[c >> 1];
            unsigned long long xv0 = pack2(v.x, v.y), xv1 = pack2(v.z, v.w);
            e0a = fma2(sW4[(c+0)*64 + lane],      xv0, e0a);
            e0b = fma2(sW4[(c+1)*64 + lane],      xv1, e0b);
            e1a = fma2(sW4[(c+0)*64 + lane + 32], xv0, e1a);
            e1b = fma2(sW4[(c+1)*64 + lane + 32], xv1, e1b);
        }
        float l0,h0,l1,h1v,l2,h2,l3,h3;
        unpack2(e0a,l0,h0); unpack2(e0b,l1,h1v); unpack2(e1a,l2,h2); unpack2(e1b,l3,h3);
        float o0 = fmaxf(sB4[lane]      + (l0+h0)+(l1+h1v), 0.0f);
        float o1 = fmaxf(sB4[lane + 32] + (l2+h2)+(l3+h3),  0.0f);
        __syncwarp();

        sOut[lane][wid]      = o0;
        sOut[lane + 32][wid] = o1;
        __syncthreads();
        for (int i = tid; i < 512; i += 256){
            int o = i >> 3, j = i & 7;
            int pp = grp*8 + j;
            int b2_ = pp / NN, n2_ = pp - b2_*NN;
            out[((long)b2_*64 + o)*NN + n2_] = sOut[o][j];
        }
        __syncthreads();
    }
}

// ---------------------------------------------------------------------------
extern "C" void kernel_launch(void* const* d_in, const int* in_sizes, int n_in,
                              void* d_out, int out_size)
{
    const float *feature=0, *xyzp=0, *W1=0, *W2=0, *W3=0, *W4=0;
    const void* neigh=0;
    const float* s32[6] = {0,0,0,0,0,0};   // g1,b1,g2,b2,g3,b3 (encounter order)
    const float* s64[2] = {0,0};           // g4,b4
    int n2048 = 0, c32 = 0, c64 = 0;
    for (int i = 0; i < n_in; i++){
        int sz = in_sizes[i];
        const float* p = (const float*)d_in[i];
        if      (sz == 10485760) feature = p;
        else if (sz == 491520)   xyzp = p;
        else if (sz == 2621440)  neigh = d_in[i];
        else if (sz == 320)      W1 = p;
        else if (sz == 2048)     { if (n2048++ == 0) W2 = p; else W3 = p; }
        else if (sz == 4096)     W4 = p;
        else if (sz == 32)       { if (c32 < 6) s32[c32++] = p; }
        else if (sz == 64)       { if (c64 < 2) s64[c64++] = p; }
    }

    kernelA<<<1184, 256>>>(feature, W2, s32[2], s32[3], W3, s32[4], (const int*)neigh);
    kernelB<<<592, 256>>>(xyzp, (const int*)neigh,
                          W1, s32[0], s32[1],
                          W3, s32[4], s32[5],
                          W4, s64[0], s64[1],
                          (float*)d_out);
}

// round 8
// speedup vs baseline: 3.0998x; 1.1377x over previous
#include <cuda_runtime.h>

#define NN 40960
#define PT (4*NN)

__device__ float g_f[(long)PT*32];   // f = relu(s2*(W2@feat)+b2), [point][32]
__device__ float g_z[(long)PT*32];   // z = s3 * (W3a @ f), [point][32]
__device__ int g_is64;

__device__ __forceinline__ unsigned long long pack2(float lo, float hi){
    unsigned long long r;
    asm("mov.b64 %0, {%1, %2};" : "=l"(r) : "f"(lo), "f"(hi));
    return r;
}
__device__ __forceinline__ void unpack2(unsigned long long v, float& lo, float& hi){
    asm("mov.b64 {%0, %1}, %2;" : "=f"(lo), "=f"(hi) : "l"(v));
}
__device__ __forceinline__ unsigned long long fma2(unsigned long long a, unsigned long long b, unsigned long long c){
    unsigned long long d;
    asm("fma.rn.f32x2 %0, %1, %2, %3;" : "=l"(d) : "l"(a), "l"(b), "l"(c));
    return d;
}

// ---------------------------------------------------------------------------
// Kernel A: per point  f = relu(s2*(W2@x)+b2);  z = s3*(W3a@f)
__global__ void __launch_bounds__(256) kernelA(
    const float* __restrict__ feat,
    const float* __restrict__ W2, const float* __restrict__ g2, const float* __restrict__ b2,
    const float* __restrict__ W3, const float* __restrict__ g3,
    const int* __restrict__ neigh32)
{
    __shared__ __align__(16) float tile[64*68];      // [n][d] pitch 68 (16B rows)
    __shared__ __align__(16) float hs[8][2][32];     // double-buffered f

    const int tid  = threadIdx.x;
    const int lane = tid & 31;
    const int wid  = tid >> 5;

    if (blockIdx.x == 0 && tid == 0){
        int allzero = 1;
        #pragma unroll 1
        for (int i = 0; i < 128; i++)
            if (neigh32[2*i + 1] != 0) { allzero = 0; break; }
        g_is64 = allzero;
    }

    const float inv = rsqrtf(1.0f + 1e-5f);
    const float s2 = g2[lane]*inv, bb2 = b2[lane];
    const float s3 = g3[lane]*inv;

    unsigned long long w2p[32], w3ap[16];
    for (int i = tid; i < 2048; i += 256) tile[(i>>6)*66 + (i&63)] = W2[i];
    __syncthreads();
    #pragma unroll
    for (int c = 0; c < 32; c++)
        w2p[c] = pack2(tile[lane*66 + 2*c]*s2, tile[lane*66 + 2*c + 1]*s2);
    __syncthreads();
    for (int i = tid; i < 2048; i += 256) tile[(i>>6)*66 + (i&63)] = W3[i];
    __syncthreads();
    #pragma unroll
    for (int c = 0; c < 16; c++)
        w3ap[c] = pack2(tile[lane*66 + 2*c]*s3, tile[lane*66 + 2*c + 1]*s3);

    #pragma unroll 1
    for (int blk = blockIdx.x; blk < 2560; blk += gridDim.x){
        const int b  = blk / 640;
        const int n0 = (blk - b*640) * 64;
        const float* fb = feat + (long)b*64*NN;
        __syncthreads();
        for (int i = tid; i < 4096; i += 256){
            int d = i >> 6, n = i & 63;
            tile[n*68 + d] = fb[(long)d*NN + n0 + n];
        }
        __syncthreads();

        #pragma unroll 1
        for (int j = 0; j < 8; j++){
            const int n = wid*8 + j;
            const ulonglong2* xp2 = (const ulonglong2*)(tile + n*68);
            unsigned long long a0=0ull, a1=0ull, a2=0ull, a3=0ull;
            #pragma unroll
            for (int c = 0; c < 16; c += 2){
                ulonglong2 v0 = xp2[c], v1 = xp2[c+1];
                a0 = fma2(w2p[2*c+0], v0.x, a0);
                a1 = fma2(w2p[2*c+1], v0.y, a1);
                a2 = fma2(w2p[2*c+2], v1.x, a2);
                a3 = fma2(w2p[2*c+3], v1.y, a3);
            }
            float l0,h0,l1,h1,l2,h2,l3,h3;
            unpack2(a0,l0,h0); unpack2(a1,l1,h1); unpack2(a2,l2,h2); unpack2(a3,l3,h3);
            float f = fmaxf((l0+h0)+(l1+h1)+(l2+h2)+(l3+h3) + bb2, 0.0f);

            const long p = (long)b*NN + n0 + n;
            float* hb = hs[wid][j & 1];
            hb[lane] = f;
            g_f[p*32 + lane] = f;
            __syncwarp();

            const ulonglong2* hp2 = (const ulonglong2*)hb;
            unsigned long long z0=0ull, z1=0ull, z2=0ull, z3=0ull;
            #pragma unroll
            for (int c = 0; c < 8; c += 2){
                ulonglong2 v0 = hp2[c], v1 = hp2[c+1];
                z0 = fma2(w3ap[2*c+0], v0.x, z0);
                z1 = fma2(w3ap[2*c+1], v0.y, z1);
                z2 = fma2(w3ap[2*c+2], v1.x, z2);
                z3 = fma2(w3ap[2*c+3], v1.y, z3);
            }
            unpack2(z0,l0,h0); unpack2(z1,l1,h1); unpack2(z2,l2,h2); unpack2(z3,l3,h3);
            g_z[p*32 + lane] = (l0+h0)+(l1+h1)+(l2+h2)+(l3+h3);
        }
    }
}

// ---------------------------------------------------------------------------
// Kernel B: persistent, one warp per point.
// Phase 0 (parallel over lanes<16): geometry (dist, r) per neighbor -> sR.
// Phase 1: per channel-lane, 16x [1 LDS.128 + 2 fma2] -> h1 -> sH1.
// Phase 2: per channel-lane, W3b @ h1_k + z_k, max over k.
__global__ void __launch_bounds__(256, 2) kernelB(
    const float* __restrict__ xyz, const int* __restrict__ neigh32,
    const float* __restrict__ W1, const float* __restrict__ g1, const float* __restrict__ b1,
    const float* __restrict__ W3, const float* __restrict__ g3, const float* __restrict__ b3,
    const float* __restrict__ W4, const float* __restrict__ g4, const float* __restrict__ b4,
    float* __restrict__ out)
{
    __shared__ __align__(16) unsigned long long sW4[32*64];  // [c_pair][o]
    __shared__ float sB4[64];
    __shared__ __align__(16) float sR[8][16*4];              // per-warp (dist,rx,ry,rz)x16
    __shared__ __align__(16) float sH1[8][16*32];            // per-warp h1[k][h]
    __shared__ __align__(16) float sE[8][64];
    __shared__ float sOut[64][9];

    const int tid  = threadIdx.x;
    const int lane = tid & 31;
    const int wid  = tid >> 5;
    const float inv = rsqrtf(1.0f + 1e-5f);

    // W1 folded weights: u=[dist,r,P,Q], Q=P-r =>
    //   W1@u = wd*dist + (Wr-WQ)@r + (WP+WQ)@P
    const float s1 = g1[lane]*inv, bb1 = b1[lane];
    const float s3 = g3[lane]*inv, bb3 = b3[lane];
    float wd   = W1[lane*10 + 0]*s1;
    float wrx  = (W1[lane*10 + 1] - W1[lane*10 + 7])*s1;
    float wry  = (W1[lane*10 + 2] - W1[lane*10 + 8])*s1;
    float wrz  = (W1[lane*10 + 3] - W1[lane*10 + 9])*s1;
    float wpx  = (W1[lane*10 + 4] + W1[lane*10 + 7])*s1;
    float wpy  = (W1[lane*10 + 5] + W1[lane*10 + 8])*s1;
    float wpz  = (W1[lane*10 + 6] + W1[lane*10 + 9])*s1;
    const unsigned long long w1a = pack2(wd,  wrx);   // * (dist, rx)
    const unsigned long long w1b = pack2(wry, wrz);   // * (ry, rz)

    unsigned long long w3bp[16];
    {
        float* wt = (float*)sW4;
        for (int i = tid; i < 2048; i += 256) wt[(i>>6)*66 + (i&63)] = W3[i];
        __syncthreads();
        #pragma unroll
        for (int c = 0; c < 16; c++)
            w3bp[c] = pack2(wt[lane*66 + 32 + 2*c]*s3, wt[lane*66 + 33 + 2*c]*s3);
        __syncthreads();
    }
    for (int i = tid; i < 2048; i += 256){
        int c2 = i >> 6, o = i & 63;
        float2 wv = ((const float2*)W4)[o*32 + c2];
        float s4 = g4[o] * inv;
        sW4[i] = pack2(wv.x*s4, wv.y*s4);
    }
    if (tid < 64) sB4[tid] = b4[tid];

    const int is64 = g_is64;
    __syncthreads();

    #pragma unroll 1
    for (int grp = blockIdx.x; grp < PT/8; grp += gridDim.x){
        const int p = grp*8 + wid;
        const int b = p / NN, n = p - b*NN;
        const float* xb = xyz + (long)b*NN*3;
        const float* zb = g_z + (long)b*NN*32;
        const float Px = xb[n*3+0], Py = xb[n*3+1], Pz = xb[n*3+2];

        // phase 0: lanes<16 compute their neighbor's geometry in parallel
        int myidx = 0;
        if (lane < 16){
            myidx = is64 ? neigh32[2*(p*16 + lane)] : neigh32[p*16 + lane];
            float Qx = xb[myidx*3+0], Qy = xb[myidx*3+1], Qz = xb[myidx*3+2];
            float rx = Px - Qx, ry = Py - Qy, rz = Pz - Qz;
            float dist = sqrtf(rx*rx + ry*ry + rz*rz);
            ((float4*)sR[wid])[lane] = make_float4(dist, rx, ry, rz);
        }

        // batched z gathers (MLP=16)
        float zk[16];
        #pragma unroll
        for (int k = 0; k < 16; k++){
            int id = __shfl_sync(0xffffffffu, myidx, k);
            zk[k] = zb[id*32 + lane];
        }
        __syncwarp();

        // per-point base: (WP+WQ)@P + bb1  (lane-specific)
        const unsigned long long basep =
            pack2(fmaf(wpx, Px, fmaf(wpy, Py, fmaf(wpz, Pz, bb1))), 0.0f);

        // phase 1: h1 for all 16 neighbors
        float* h1w = sH1[wid];
        const ulonglong2* rp = (const ulonglong2*)sR[wid];
        #pragma unroll
        for (int k = 0; k < 16; k++){
            ulonglong2 rv = rp[k];                 // (dist,rx),(ry,rz) broadcast
            unsigned long long acc = fma2(w1a, rv.x, basep);
            acc = fma2(w1b, rv.y, acc);
            float lo, hi; unpack2(acc, lo, hi);
            h1w[k*32 + lane] = fmaxf(lo + hi, 0.0f);
        }
        __syncwarp();

        // phase 2: y_k = z_k + W3b @ h1_k ; max over k (b3 hoisted)
        float maxv = -3.4e38f;
        #pragma unroll
        for (int k = 0; k < 16; k++){
            const ulonglong2* hp2 = (const ulonglong2*)(h1w + k*32);
            unsigned long long c0=0ull, c1=0ull, c2=0ull, c3=0ull;
            #pragma unroll
            for (int c = 0; c < 8; c += 2){
                ulonglong2 v0 = hp2[c], v1 = hp2[c+1];
                c0 = fma2(w3bp[2*c+0], v0.x, c0);
                c1 = fma2(w3bp[2*c+1], v0.y, c1);
                c2 = fma2(w3bp[2*c+2], v1.x, c2);
                c3 = fma2(w3bp[2*c+3], v1.y, c3);
            }
            float l0,h0,l1,h1v,l2,h2,l3,h3;
            unpack2(c0,l0,h0); unpack2(c1,l1,h1v); unpack2(c2,l2,h2); unpack2(c3,l3,h3);
            float y = zk[k] + (l0+h0)+(l1+h1v)+(l2+h2)+(l3+h3);
            maxv = fmaxf(maxv, y);
        }
        maxv = fmaxf(maxv + bb3, 0.0f);   // relu commutes with max

        const float fself = g_f[(long)p*32 + lane];
        sE[wid][lane]      = maxv;
        sE[wid][32 + lane] = fself;
        __syncwarp();
        const ulonglong2* ep2 = (const ulonglong2*)sE[wid];
        unsigned long long e0a=0ull, e0b=0ull, e1a=0ull, e1b=0ull;
        #pragma unroll
        for (int c = 0; c < 32; c += 2){
            ulonglong2 v = ep2[c >> 1];
            e0a = fma2(sW4[(c+0)*64 + lane],      v.x, e0a);
            e0b = fma2(sW4[(c+1)*64 + lane],      v.y, e0b);
            e1a = fma2(sW4[(c+0)*64 + lane + 32], v.x, e1a);
            e1b = fma2(sW4[(c+1)*64 + lane + 32], v.y, e1b);
        }
        float l0,h0,l1,h1v,l2,h2,l3,h3;
        unpack2(e0a,l0,h0); unpack2(e0b,l1,h1v); unpack2(e1a,l2,h2); unpack2(e1b,l3,h3);
        float o0 = fmaxf(sB4[lane]      + (l0+h0)+(l1+h1v), 0.0f);
        float o1 = fmaxf(sB4[lane + 32] + (l2+h2)+(l3+h3),  0.0f);
        __syncwarp();

        sOut[lane][wid]      = o0;
        sOut[lane + 32][wid] = o1;
        __syncthreads();
        for (int i = tid; i < 512; i += 256){
            int o = i >> 3, j = i & 7;
            int pp = grp*8 + j;
            int b2_ = pp / NN, n2_ = pp - b2_*NN;
            out[((long)b2_*64 + o)*NN + n2_] = sOut[o][j];
        }
        __syncthreads();
    }
}

// ---------------------------------------------------------------------------
extern "C" void kernel_launch(void* const* d_in, const int* in_sizes, int n_in,
                              void* d_out, int out_size)
{
    const float *feature=0, *xyzp=0, *W1=0, *W2=0, *W3=0, *W4=0;
    const void* neigh=0;
    const float* s32[6] = {0,0,0,0,0,0};   // g1,b1,g2,b2,g3,b3 (encounter order)
    const float* s64[2] = {0,0};           // g4,b4
    int n2048 = 0, c32 = 0, c64 = 0;
    for (int i = 0; i < n_in; i++){
        int sz = in_sizes[i];
        const float* p = (const float*)d_in[i];
        if      (sz == 10485760) feature = p;
        else if (sz == 491520)   xyzp = p;
        else if (sz == 2621440)  neigh = d_in[i];
        else if (sz == 320)      W1 = p;
        else if (sz == 2048)     { if (n2048++ == 0) W2 = p; else W3 = p; }
        else if (sz == 4096)     W4 = p;
        else if (sz == 32)       { if (c32 < 6) s32[c32++] = p; }
        else if (sz == 64)       { if (c64 < 2) s64[c64++] = p; }
    }

    kernelA<<<1184, 256>>>(feature, W2, s32[2], s32[3], W3, s32[4], (const int*)neigh);
    kernelB<<<592, 256>>>(xyzp, (const int*)neigh,
                          W1, s32[0], s32[1],
                          W3, s32[4], s32[5],
                          W4, s64[0], s64[1],
                          (float*)d_out);
}